// round 12
// baseline (speedup 1.0000x reference)
#include <cuda_runtime.h>
#include <cuda_bf16.h>

// QuantumConv2d on GB300 — merged 2-qubit RX stages, packed complex f32x2.
//
// Per 2x2 patch (x0,x1,x2,x3):
//   t_k = A[k&3] + B[k>>2]  (signed sums, sign + iff bit set, LSB-first)
//   phase_k = -(t/2 + t^2/4)          [global phase dropped]
//   d_k = exp(i phase_k)
//   y = (RX(w3)(x)RX(w2)(x)RX(w1)(x)RX(w0)) d, applied as TWO 2-qubit stages:
//     stage pair (lo,hi) on quadruple (a,b,c,d)=(k, k^lo, k^hi, k^lo^hi):
//       y_a = cc a - i(ch sl) b - i(sh cl) c - (sh sl) d   (and cyclic variants)
//     packed (re,im): -i k x = k*(xi, -xr) = (k,-k) .* swap(x);  -ss x plain.
//   0.25 initial-state amplitude folded into the second stage-pair coeffs.
//   state_{F(j)} = y_j, F = CNOT-ring perm {0,14,15,1,13,3,2,12,9,7,6,8,4,10,11,5}
//   out_q = sum_{j: bit(3-q) of F(j)} |y_j|^2
//
// History: R7 scalar-phase/epilogue + packed RX = best body; R8/R9 packing of
// scalar sections and R10 persistent grid regressed; R11 128-thr blocks won.
// R12: merge stages 2x2 — same packed op count, half the swap MOVs and half
// the stage dependency depth.

#define PK2(d, lo, hi)   asm("mov.b64 %0, {%1, %2};" : "=l"(d) : "f"(lo), "f"(hi))
#define UPK2(lo, hi, d)  asm("mov.b64 {%0, %1}, %2;" : "=f"(lo), "=f"(hi) : "l"(d))
#define MUL2(d, a, b)    asm("mul.rn.f32x2 %0, %1, %2;" : "=l"(d) : "l"(a), "l"(b))
#define FMA2(d, a, b, c) asm("fma.rn.f32x2 %0, %1, %2, %3;" : "=l"(d) : "l"(a), "l"(b), "l"(c))

#define TPB 128

// one 2-qubit stage on quadruple indices i0,i1,i2,i3 (i1=i0^lo, i2=i0^hi, i3=i0^lo^hi)
#define QSTAGE(i0, i1, i2, i3, CC, CS, SC, NSS) do {                         \
    unsigned long long a = v[i0], b = v[i1], cq_ = v[i2], dq_ = v[i3];       \
    float ar, ai, br, bi, cr, ci, drr, dii;                                  \
    UPK2(ar, ai, a);  UPK2(br, bi, b);                                       \
    UPK2(cr, ci, cq_); UPK2(drr, dii, dq_);                                  \
    unsigned long long sa, sb, sc, sd;                                       \
    PK2(sa, ai, ar);  PK2(sb, bi, br);                                       \
    PK2(sc, ci, cr);  PK2(sd, dii, drr);                                     \
    unsigned long long ya, yb, yc, yd;                                       \
    MUL2(ya, a, CC);   FMA2(ya, dq_, NSS, ya);                               \
    FMA2(ya, sb, CS, ya);  FMA2(ya, sc, SC, ya);                             \
    MUL2(yb, b, CC);   FMA2(yb, cq_, NSS, yb);                               \
    FMA2(yb, sa, CS, yb);  FMA2(yb, sd, SC, yb);                             \
    MUL2(yc, cq_, CC); FMA2(yc, b, NSS, yc);                                 \
    FMA2(yc, sd, CS, yc);  FMA2(yc, sa, SC, yc);                             \
    MUL2(yd, dq_, CC); FMA2(yd, a, NSS, yd);                                 \
    FMA2(yd, sc, CS, yd);  FMA2(yd, sb, SC, yd);                             \
    v[i0] = ya; v[i1] = yb; v[i2] = yc; v[i3] = yd;                          \
} while (0)

__global__ __launch_bounds__(TPB) void qconv_kernel(const float* __restrict__ x,
                                                    const float* __restrict__ w,
                                                    float4* __restrict__ out) {
    // per-thread RX coefficients
    float c0, s0, c1, s1, c2, s2, c3, s3;
    __sincosf(0.5f * w[0], &s0, &c0);
    __sincosf(0.5f * w[1], &s1, &c1);
    __sincosf(0.5f * w[2], &s2, &c2);
    __sincosf(0.5f * w[3], &s3, &c3);

    int tid = blockIdx.x * TPB + threadIdx.x;   // = b*16384 + jj*128 + ii
    int b  = tid >> 14;
    int jj = (tid >> 7) & 127;
    int ii = tid & 127;

    const float* p = x + (b << 16) + (jj << 9) + (ii << 1);
    float2 a01 = *(const float2*)(p);
    float2 a23 = *(const float2*)(p + 256);
    float x0 = a01.x, x1 = a01.y, x2 = a23.x, x3 = a23.y;

    float A[4] = {-x0 - x1,  x0 - x1, -x0 + x1,  x0 + x1};
    float B[4] = {-x2 - x3,  x2 - x3, -x2 + x3,  x2 + x3};

    // phases + cis (scalar — measured best)
    unsigned long long v[16];   // packed (re, im)
    #pragma unroll
    for (int k = 0; k < 16; k++) {
        float t  = A[k & 3] + B[k >> 2];
        float ph = t * fmaf(-0.25f, t, -0.5f);   // -(t/2 + t^2/4)
        float sn, cs;
        __sincosf(ph, &sn, &cs);
        PK2(v[k], cs, sn);
    }

    // stage pair A: qubits 0 (lo, w0) and 1 (hi, w1)
    {
        float cc = c1 * c0, ss = s1 * s0, cs_ = c1 * s0, sc_ = s1 * c0;
        float ncc_s = -ss, ncs = -cs_, nsc = -sc_;
        unsigned long long CC, NSS, CS, SC;
        PK2(CC, cc, cc);
        PK2(NSS, ncc_s, ncc_s);
        PK2(CS, cs_, ncs);     // (k, -k) pattern for -i k swap(x)
        PK2(SC, sc_, nsc);
        QSTAGE( 0,  1,  2,  3, CC, CS, SC, NSS);
        QSTAGE( 4,  5,  6,  7, CC, CS, SC, NSS);
        QSTAGE( 8,  9, 10, 11, CC, CS, SC, NSS);
        QSTAGE(12, 13, 14, 15, CC, CS, SC, NSS);
    }

    // stage pair B: qubits 2 (lo, w2) and 3 (hi, w3); 0.25 amplitude folded in
    {
        float cc = 0.25f * c3 * c2, ss = 0.25f * s3 * s2;
        float cs_ = 0.25f * c3 * s2, sc_ = 0.25f * s3 * c2;
        float nss = -ss, ncs = -cs_, nsc = -sc_;
        unsigned long long CC, NSS, CS, SC;
        PK2(CC, cc, cc);
        PK2(NSS, nss, nss);
        PK2(CS, cs_, ncs);
        PK2(SC, sc_, nsc);
        QSTAGE(0, 4,  8, 12, CC, CS, SC, NSS);
        QSTAGE(1, 5,  9, 13, CC, CS, SC, NSS);
        QSTAGE(2, 6, 10, 14, CC, CS, SC, NSS);
        QSTAGE(3, 7, 11, 15, CC, CS, SC, NSS);
    }

    // probabilities (scalar, wide ILP)
    float pr[16];
    #pragma unroll
    for (int j = 0; j < 16; j++) {
        float re, im;
        UPK2(re, im, v[j]);
        pr[j] = fmaf(re, re, im * im);
    }

    // grouped accumulation through F = {0,14,15,1,13,3,2,12,9,7,6,8,4,10,11,5}
    float T1 = pr[9]  + pr[10] + pr[12] + pr[15];
    float T2 = pr[8]  + pr[11] + pr[13] + pr[14];
    float T3 = pr[1]  + pr[2]  + pr[4]  + pr[7];
    float U1 = pr[3]  + pr[4]  + pr[8]  + pr[15];
    float U2 = pr[1]  + pr[6]  + pr[10] + pr[13];
    float U3 = pr[2]  + pr[5]  + pr[9]  + pr[14];
    float o0 = T2 + T3;   // bit 3 of F(j)
    float o1 = T1 + T3;   // bit 2
    float o2 = U2 + U3;   // bit 1
    float o3 = U1 + U3;   // bit 0

    out[tid] = make_float4(o0, o1, o2, o3);
}

extern "C" void kernel_launch(void* const* d_in, const int* in_sizes, int n_in,
                              void* d_out, int out_size) {
    const float* x = (const float*)d_in[0];
    const float* w = (const float*)d_in[1];
    if (n_in >= 2 && in_sizes[0] == 4) {   // robustness if metadata order differs
        x = (const float*)d_in[1];
        w = (const float*)d_in[0];
    }
    qconv_kernel<<<8192, TPB>>>(x, w, (float4*)d_out);
}

// round 13
// speedup vs baseline: 1.0118x; 1.0118x over previous
#include <cuda_runtime.h>
#include <cuda_bf16.h>

// QuantumConv2d on GB300 — direct tensor-product RX application (no WHT, no smem).
//
// Per 2x2 patch (x0,x1,x2,x3):
//   t_k = +-x0 +-x1 +-x2 +-x3  (sign + iff bit q of k set, LSB-first)
//   phase_k = -(t/2 + t^2/4)          [global phase dropped]
//   d_k = exp(i phase_k)
//   y = (RX(w3)(x)RX(w2)(x)RX(w1)(x)RX(w0)) d as 4 commuting single-qubit
//       stages: pair (a, b=a^2^q): y_a = c a - i s b, y_b = -i s a + c b.
//       Packed (re,im): -i s b = (s*bi, -s*br) = (s,-s) .* swap(b)
//   0.25 initial-state amplitude folded into stage-3 coefficients.
//   state_{F(j)} = y_j, F = CNOT-ring perm {0,14,15,1,13,3,2,12,9,7,6,8,4,10,11,5}
//   out_q = sum_{j: bit(3-q) of F(j)} |y_j|^2
//
// Session law (R8/R9/R10/R12 regressions): keep the dependency graph wide and
// shallow; pack only where data already lives as aligned complex pairs.
// R13 = R11 + (a) PMQR t-gen (-4 instr, same shape) and (b) packed |.|^2 via
// MUL2 on the already-paired v regs (-16 instr, unpack aliases to zero SASS),
// keeping R11's wide scalar add tree.

#define PK2(d, lo, hi)   asm("mov.b64 %0, {%1, %2};" : "=l"(d) : "f"(lo), "f"(hi))
#define UPK2(lo, hi, d)  asm("mov.b64 {%0, %1}, %2;" : "=f"(lo), "=f"(hi) : "l"(d))
#define MUL2(d, a, b)    asm("mul.rn.f32x2 %0, %1, %2;" : "=l"(d) : "l"(a), "l"(b))
#define FMA2(d, a, b, c) asm("fma.rn.f32x2 %0, %1, %2, %3;" : "=l"(d) : "l"(a), "l"(b), "l"(c))

#define TPB 128

__global__ __launch_bounds__(TPB) void qconv_kernel(const float* __restrict__ x,
                                                    const float* __restrict__ w,
                                                    float4* __restrict__ out) {
    // per-thread RX coefficients (w is uniform -> L1/L2 cached)
    float c[4], s[4];
    #pragma unroll
    for (int q = 0; q < 4; q++)
        __sincosf(0.5f * w[q], &s[q], &c[q]);
    c[3] *= 0.25f;   // fold |psi0| amplitude into last stage
    s[3] *= 0.25f;

    int tid = blockIdx.x * TPB + threadIdx.x;   // = b*16384 + jj*128 + ii
    int b  = tid >> 14;
    int jj = (tid >> 7) & 127;
    int ii = tid & 127;

    const float* p = x + (b << 16) + (jj << 9) + (ii << 1);
    float2 a01 = *(const float2*)(p);
    float2 a23 = *(const float2*)(p + 256);
    float x0 = a01.x, x1 = a01.y, x2 = a23.x, x3 = a23.y;

    // t_k from P/M/Q/R (FADD source-negation folds; same depth as A/B form)
    float P = x0 + x1, M = x0 - x1, Q = x2 + x3, R = x2 - x3;
    float t[16];
    t[0]  = -P - Q;  t[1]  =  M - Q;  t[2]  = -M - Q;  t[3]  =  P - Q;
    t[4]  =  R - P;  t[5]  =  M + R;  t[6]  =  R - M;  t[7]  =  P + R;
    t[8]  = -P - R;  t[9]  =  M - R;  t[10] = -M - R;  t[11] =  P - R;
    t[12] =  Q - P;  t[13] =  M + Q;  t[14] =  Q - M;  t[15] =  P + Q;

    // phases + cis (scalar — measured best across R8/R9 variants)
    unsigned long long v[16];   // packed (re, im)
    #pragma unroll
    for (int k = 0; k < 16; k++) {
        float ph = t[k] * fmaf(-0.25f, t[k], -0.5f);   // -(t/2 + t^2/4)
        float sn, cs;
        __sincosf(ph, &sn, &cs);
        PK2(v[k], cs, sn);
    }

    // 4 single-qubit RX stages (commuting), packed complex — R11 form
    #pragma unroll
    for (int q = 0; q < 4; q++) {
        int m = 1 << q;
        float cq = c[q], sq = s[q], nsq = -s[q];
        unsigned long long C2, S2;
        PK2(C2, cq, cq);      // (c,  c)
        PK2(S2, sq, nsq);     // (s, -s)
        #pragma unroll
        for (int k = 0; k < 16; k++) {
            if (!(k & m)) {
                unsigned long long a = v[k], bb = v[k | m];
                float ar, ai, br, bi;
                UPK2(ar, ai, a);
                UPK2(br, bi, bb);
                unsigned long long sa, sb;        // swapped halves (ALU MOVs)
                PK2(sa, ai, ar);
                PK2(sb, bi, br);
                unsigned long long ta, tb, ya, yb;
                MUL2(ta, a, C2);
                MUL2(tb, bb, C2);
                FMA2(ya, sb, S2, ta);             // c*a + (s*bi, -s*br)
                FMA2(yb, sa, S2, tb);             // c*b + (s*ai, -s*ar)
                v[k] = ya; v[k | m] = yb;
            }
        }
    }

    // packed squares (re^2, im^2) — inputs/outputs alias register pairs, so the
    // unpack below is free; the add tree stays wide scalar (R11 form).
    float r2[16], i2[16];
    #pragma unroll
    for (int j = 0; j < 16; j++) {
        unsigned long long sqp;
        MUL2(sqp, v[j], v[j]);
        UPK2(r2[j], i2[j], sqp);
    }

    // grouped accumulation through F = {0,14,15,1,13,3,2,12,9,7,6,8,4,10,11,5}
    // pr[j] = r2[j] + i2[j], folded into the wide sums
    float T1 = (r2[9]  + i2[9])  + (r2[10] + i2[10]) + (r2[12] + i2[12]) + (r2[15] + i2[15]);
    float T2 = (r2[8]  + i2[8])  + (r2[11] + i2[11]) + (r2[13] + i2[13]) + (r2[14] + i2[14]);
    float T3 = (r2[1]  + i2[1])  + (r2[2]  + i2[2])  + (r2[4]  + i2[4])  + (r2[7]  + i2[7]);
    float U1 = (r2[3]  + i2[3])  + (r2[4]  + i2[4])  + (r2[8]  + i2[8])  + (r2[15] + i2[15]);
    float U2 = (r2[1]  + i2[1])  + (r2[6]  + i2[6])  + (r2[10] + i2[10]) + (r2[13] + i2[13]);
    float U3 = (r2[2]  + i2[2])  + (r2[5]  + i2[5])  + (r2[9]  + i2[9])  + (r2[14] + i2[14]);
    float o0 = T2 + T3;   // bit 3 of F(j)
    float o1 = T1 + T3;   // bit 2
    float o2 = U2 + U3;   // bit 1
    float o3 = U1 + U3;   // bit 0

    out[tid] = make_float4(o0, o1, o2, o3);
}

extern "C" void kernel_launch(void* const* d_in, const int* in_sizes, int n_in,
                              void* d_out, int out_size) {
    const float* x = (const float*)d_in[0];
    const float* w = (const float*)d_in[1];
    if (n_in >= 2 && in_sizes[0] == 4) {   // robustness if metadata order differs
        x = (const float*)d_in[1];
        w = (const float*)d_in[0];
    }
    qconv_kernel<<<8192, TPB>>>(x, w, (float4*)d_out);
}